// round 2
// baseline (speedup 1.0000x reference)
#include <cuda_runtime.h>

#define NCLS  19
#define DIM   256
#define NPIX  4096
#define NBINS 51
#define NW    (NCLS * DIM)   // 4864 (c,d) tasks

// ---- scratch (no allocations allowed) ----
__device__ int   g_perm[NPIX];
__device__ int   g_off[NCLS + 1];
__device__ int   g_cnt[NCLS];
__device__ float g_Fs[DIM * NPIX];        // class-sorted, d-major
__device__ float g_S[NW * NBINS];         // unnormalized sample histograms
__device__ float g_miu[NW];
__device__ float g_var[NW];
__device__ float g_clsum[NCLS];

__device__ __forceinline__ float wredsum(float v) {
#pragma unroll
    for (int m = 16; m; m >>= 1) v += __shfl_xor_sync(0xffffffffu, v, m);
    return v;
}

__device__ __forceinline__ float ex2(float x) {
    float e;
    asm("ex2.approx.ftz.f32 %0, %1;" : "=f"(e) : "f"(x));
    return e;
}

// K0: sniff label dtype (int64 vs int32), histogram + counting sort of pixel
// indices by class; zero accumulators.
// Dtype sniff: as int32 words, an int64 label array (values 0..18) has ALL odd
// words == 0. An int32 label array has labels at odd words (random 0..18,
// P(all zero) ~ 0). We only touch words [0,4096) which is in-bounds for both
// interpretations (int32: exactly 4096 words; int64: 8192 words).
__global__ void k_prep(const int* __restrict__ lab32) {
    __shared__ int shist[NCLS];
    __shared__ int scur[NCLS];
    __shared__ short slab[NPIX];
    int t = threadIdx.x;

    int any = 0;
    for (int i = 2 * t + 1; i < NPIX; i += 2 * blockDim.x) any |= lab32[i];
    int is32 = __syncthreads_or(any);

    if (t < NCLS) shist[t] = 0;
    __syncthreads();
    for (int n = t; n < NPIX; n += blockDim.x) {
        int c = is32 ? lab32[n] : lab32[2 * n];   // int64: low word
        c = max(0, min(NCLS - 1, c));
        slab[n] = (short)c;
        atomicAdd(&shist[c], 1);
    }
    __syncthreads();
    if (t == 0) {
        int off = 0;
        for (int c = 0; c < NCLS; c++) {
            g_cnt[c] = shist[c];
            g_off[c] = off;
            scur[c]  = off;
            off += shist[c];
        }
        g_off[NCLS] = off;
    }
    if (t < NCLS) g_clsum[t] = 0.f;
    __syncthreads();
    for (int n = t; n < NPIX; n += blockDim.x) {
        int c = slab[n];
        int r = atomicAdd(&scur[c], 1);
        g_perm[r] = n;
    }
}

// KT: gather feature into class-sorted order, d-major. Coalesced writes,
// gathers stay inside one 16KB row (L1/L2-resident).
__global__ void k_gather(const float* __restrict__ feature) {
    int d = blockIdx.x;
    const float* __restrict__ src = feature + d * NPIX;
    float* __restrict__ dst = g_Fs + d * NPIX;
    for (int j = threadIdx.x; j < NPIX; j += blockDim.x)
        dst[j] = src[g_perm[j]];
}

// K3 (heavy): one warp per (c,d). Fused class stats + 51-bin KDE accumulation.
// Per (pixel,bin): 2 FFMA(imm) + EX2 + FADD  -> MUFU-bound.
__global__ void __launch_bounds__(128) k_main() {
    int w = blockIdx.x * 4 + (threadIdx.x >> 5);
    if (w >= NW) return;
    int lane = threadIdx.x & 31;
    int c = w >> 8;        // 4864 = 19*256
    int d = w & 255;
    int off = g_off[c];
    int cnt = g_off[c + 1] - off;
    if (cnt == 0) return;

    const float* __restrict__ fp = g_Fs + d * NPIX + off;

    // pass 1: per-class mean/var for this feature dim
    float s1 = 0.f, s2 = 0.f;
    for (int i = lane; i < cnt; i += 32) {
        float f = fp[i];
        s1 += f;
        s2 = fmaf(f, f, s2);
    }
    s1 = wredsum(s1);
    s2 = wredsum(s2);
    float cm  = (float)cnt;
    float miu = s1 / cm;
    float var = fmaxf(s2 / cm - miu * miu, 1e-12f);
    if (lane == 0) { g_miu[w] = miu; g_var[w] = var; }

    const float LOG2E = 1.4426950408889634f;
    // vs = var/25 ; exponent coef (base-2): -0.5/vs * log2e = -12.5*log2e/var
    float a_s = -12.5f * LOG2E / var;

    float acc[NBINS];
#pragma unroll
    for (int k = 0; k < NBINS; k++) acc[k] = 0.f;

    // pass 2: KDE accumulation. arg = a_s*bk^2 + p1*bk + p0 (bk, bk^2 are imm).
    for (int i = lane; i < cnt; i += 32) {
        float f  = fp[i];
        float p1 = (-2.f * a_s) * f;
        float p0 = a_s * f * f;
#pragma unroll
        for (int k = 0; k < NBINS; k++) {
            float bk  = -5.f + 0.2f * (float)k;
            float arg = fmaf(a_s, bk * bk, fmaf(p1, bk, p0));
            acc[k] += ex2(arg);
        }
    }

#pragma unroll
    for (int k = 0; k < NBINS; k++) acc[k] = wredsum(acc[k]);

    float* __restrict__ Sp = g_S + w * NBINS;
    if (lane == 0) {
#pragma unroll
        for (int k = 0; k < NBINS; k++) Sp[k] = acc[k];
    }
}

// K3b: epilogue with bins mapped to lanes (lane k handles bins k and k+32).
// Normalize sample hist, build normalized gaussian target, smooth-L1 sum.
__global__ void __launch_bounds__(128) k_epi() {
    int w = blockIdx.x * 4 + (threadIdx.x >> 5);
    if (w >= NW) return;
    int lane = threadIdx.x & 31;
    int c = w >> 8;
    if (g_cnt[c] == 0) return;

    const float* __restrict__ Sp = g_S + w * NBINS;
    bool hi = lane < (NBINS - 32);  // lanes 0..18 also own bins 32..50
    float s0 = Sp[lane];
    float s1 = hi ? Sp[lane + 32] : 0.f;
    float sumS = wredsum(s0 + s1);

    float miu = g_miu[w];
    float var = g_var[w];
    const float LOG2E = 1.4426950408889634f;
    float at = -0.5f * LOG2E / var;

    float b0 = fmaf(0.2f, (float)lane, -5.f);
    float b1 = b0 + 6.4f;                     // bin lane+32
    float d0 = b0 - miu, d1 = b1 - miu;
    float g0 = ex2(at * d0 * d0);
    float g1 = hi ? ex2(at * d1 * d1) : 0.f;
    float sumT = wredsum(g0 + g1);

    float invS = 1.f / fmaxf(sumS, 1e-30f);
    float invT = 1.f / fmaxf(sumT, 1e-30f);

    float df0 = s0 * invS - g0 * invT;
    float df1 = s1 * invS - g1 * invT;
    float ad0 = fabsf(df0), ad1 = fabsf(df1);
    float l0 = (ad0 < 1.f) ? 0.5f * df0 * df0 : ad0 - 0.5f;
    float l1 = (ad1 < 1.f) ? 0.5f * df1 * df1 : ad1 - 0.5f;
    if (!hi) l1 = 0.f;

    float sl = wredsum(l0 + l1);
    if (lane == 0) atomicAdd(&g_clsum[c], sl);
}

// K4: active-class masked mean -> loss scalar.
__global__ void k_final(float* __restrict__ out) {
    int lane = threadIdx.x;
    float v = 0.f, a = 0.f;
    if (lane >= 1 && lane < NCLS && g_cnt[lane] > 0) {
        v = g_clsum[lane] * (1.f / 13056.f);   // / (D*B)
        a = 1.f;
    }
    v = wredsum(v);
    a = wredsum(a);
    if (lane == 0) out[0] = v / (a + 1e-12f);  // LOSS_WEIGHT = 1
}

extern "C" void kernel_launch(void* const* d_in, const int* in_sizes, int n_in,
                              void* d_out, int out_size) {
    // Inputs per metadata order: feature (1048576 f32), label (4096 elems).
    // Label element count may read 4096 (i64 or i32) or 8192 (i64 viewed as
    // i32); the smaller buffer is the label either way.
    int fi = 0, li = 1;
    if (n_in >= 2 && in_sizes[0] < in_sizes[1]) { fi = 1; li = 0; }
    const float* feature = (const float*)d_in[fi];
    const int*   label   = (const int*)d_in[li];
    float* out = (float*)d_out;

    k_prep<<<1, 1024>>>(label);
    k_gather<<<DIM, 256>>>(feature);
    k_main<<<(NW + 3) / 4, 128>>>();
    k_epi<<<(NW + 3) / 4, 128>>>();
    k_final<<<1, 32>>>(out);

    // Output layout: [loss, feature...]
    if (out_size > 1) {
        size_t nf = (size_t)(out_size - 1);
        size_t cap = (size_t)DIM * NPIX;
        if (nf > cap) nf = cap;
        cudaMemcpyAsync(out + 1, feature, nf * sizeof(float),
                        cudaMemcpyDeviceToDevice);
    }
}